// round 12
// baseline (speedup 1.0000x reference)
#include <cuda_runtime.h>
#include <cstdint>

#define T_ 512
#define B_ 256
#define D_ 128
#define H_ 256
#define P_ 128
#define M_ (T_*B_)
#define NBLK 128
#define NTHR 256
#define BH_ (B_*H_)
#define NGRP 32           // 32 groups x 4 CTAs, 8 batch rows (4 per set)
#define GBLK 4
#define SLICE_F 520       // 128p*4rows + 4 hsq + pad

typedef unsigned long long ull;

// ---------------- scratch ---------------------------------------------------
__device__ float g_A[(size_t)T_*B_*P_];
__device__ float g_xsq[M_];
__device__ float g_psum[P_];
__device__ float g_part[2*NGRP*2*GBLK*SLICE_F];  // [buf][grp][set][cta][520]
__device__ unsigned int g_flags[2*NGRP*32];      // [set][grp][32] (words 0..3)

// ---------------- helpers ---------------------------------------------------
__device__ __forceinline__ ull pack2(float lo, float hi) {
    ull r; asm("mov.b64 %0, {%1, %2};" : "=l"(r) : "f"(lo), "f"(hi)); return r;
}
__device__ __forceinline__ void unpack2(ull v, float& lo, float& hi) {
    asm("mov.b64 {%0, %1}, %2;" : "=f"(lo), "=f"(hi) : "l"(v));
}
__device__ __forceinline__ ull fma2(ull a, ull b, ull c) {
    ull d; asm("fma.rn.f32x2 %0, %1, %2, %3;" : "=l"(d) : "l"(a), "l"(b), "l"(c));
    return d;
}
__device__ __forceinline__ float sigf(float x) {
    return __fdividef(1.f, 1.f + __expf(-x));
}
__device__ __forceinline__ float tanh_fast(float x) {
    float e = __expf(2.f * x);
    return 1.f - __fdividef(2.f, e + 1.f);
}

// ---------------- precompute kernels (unchanged) ----------------------------
__global__ void xsq_kernel(const float* __restrict__ x) {
    int warp = (blockIdx.x * blockDim.x + threadIdx.x) >> 5;
    int lane = threadIdx.x & 31;
    if (warp >= M_) return;
    const float* row = x + (size_t)warp * D_;
    float s = 0.f;
#pragma unroll
    for (int i = 0; i < 4; i++) { float v = row[lane + 32*i]; s += v*v; }
#pragma unroll
    for (int o = 16; o; o >>= 1) s += __shfl_down_sync(0xffffffffu, s, o);
    if (lane == 0) g_xsq[warp] = s;
}

__global__ void psum_kernel(const float* __restrict__ proto) {
    int p = threadIdx.x;
    if (p >= P_) return;
    const float* row = proto + (size_t)p * (D_ + H_);
    float s = 0.f;
    for (int i = 0; i < D_ + H_; i++) { float v = row[i]; s += v*v; }
    g_psum[p] = s;
}

__global__ void agemm_kernel(const float* __restrict__ x,
                             const float* __restrict__ proto) {
    __shared__ float sX[64][33];
    __shared__ float sP[32][132];
    const int tid = threadIdx.x;
    const int tx = tid & 31;
    const int ty = tid >> 5;
    const int m0 = blockIdx.x * 64;

    float acc[8][4];
#pragma unroll
    for (int r = 0; r < 8; r++)
#pragma unroll
        for (int q = 0; q < 4; q++) acc[r][q] = 0.f;

    for (int k0 = 0; k0 < D_; k0 += 32) {
#pragma unroll
        for (int i = 0; i < 8; i++) {
            int e = tid + i * 256;
            int r = e >> 5, c = e & 31;
            sX[r][c] = x[(size_t)(m0 + r) * D_ + k0 + c];
        }
#pragma unroll
        for (int i = 0; i < 16; i++) {
            int e = tid + i * 256;
            int p = e >> 5, c = e & 31;
            sP[c][p] = proto[(size_t)p * (D_ + H_) + k0 + c];
        }
        __syncthreads();
#pragma unroll
        for (int kc = 0; kc < 32; kc++) {
            float4 b4 = *(const float4*)&sP[kc][tx * 4];
#pragma unroll
            for (int r = 0; r < 8; r++) {
                float a = sX[ty * 8 + r][kc];
                acc[r][0] += a * b4.x; acc[r][1] += a * b4.y;
                acc[r][2] += a * b4.z; acc[r][3] += a * b4.w;
            }
        }
        __syncthreads();
    }
#pragma unroll
    for (int r = 0; r < 8; r++) {
        int row = m0 + ty * 8 + r;
        float xs = g_xsq[row];
        float4 o;
        o.x = xs + g_psum[tx*4+0] - 2.f * acc[r][0];
        o.y = xs + g_psum[tx*4+1] - 2.f * acc[r][1];
        o.z = xs + g_psum[tx*4+2] - 2.f * acc[r][2];
        o.w = xs + g_psum[tx*4+3] - 2.f * acc[r][3];
        *(float4*)&g_A[(size_t)row * P_ + tx * 4] = o;
    }
}

__global__ void zero_flags_kernel() {
    int i = blockIdx.x * blockDim.x + threadIdx.x;
    if (i < 2*NGRP*32) g_flags[i] = 0;
}

// ---------------- main persistent recurrent kernel -------------------------
// smem floats: s_pH 8704 | s_W 32768 | s_hA 272 | s_hB 272 | s_kA 528 | s_kB 528
#define SMEM_FLOATS (8704 + 32768 + 272 + 272 + 528 + 528)

__global__ void __launch_bounds__(NTHR, 1)
qlstm_main(const float* __restrict__ proto,
           const float* __restrict__ Wf_, const float* __restrict__ bf_,
           const float* __restrict__ Wi_, const float* __restrict__ bi_,
           const float* __restrict__ Wg_, const float* __restrict__ bg_,
           const float* __restrict__ Wo_, const float* __restrict__ bo_,
           float* __restrict__ out) {
    extern __shared__ float sm[];
    float* s_pH = sm;                   // [128 p][68] staging for reg preload
    float* s_W  = sm + 8704;            // [p][u*4+gate], 256 cols
    float* s_hA = sm + 41472;           // [4 rows][68]
    float* s_hB = s_hA + 272;
    float* s_kA = s_hB + 272;           // [4 rows][132]  k in [row][p]
    float* s_kB = s_kA + 528;

    const int tid = threadIdx.x;
    const int bid = blockIdx.x;
    const int grp = bid >> 2;
    const int sub = bid & 3;

    // phase-1 / reduce role: thread = (p, rh) -> rows rh*2, rh*2+1 of the set
    const int p1p = tid >> 1;
    const int rh  = tid & 1;
    // phase-2 role: warp = 8 units x 4 rows
    const int w    = tid >> 5;
    const int lane = tid & 31;
    const int unit = w * 8 + (lane & 7);      // 0..63
    const int prow = lane >> 3;               // 0..3
    const int gu   = sub * 64 + unit;
    const int idxA = (grp * 8 + prow) * H_ + gu;
    const int idxB = idxA + 4 * H_;

    // ---- persistent SMEM fills ----
    for (int i = tid; i < 128 * 64; i += NTHR) {
        int p = i >> 6, j = i & 63;
        s_pH[p * 68 + j] = proto[(size_t)p * (D_ + H_) + D_ + sub * 64 + j];
    }
#pragma unroll
    for (int g = 0; g < 4; g++) {
        const float* Wp = (g == 0) ? Wf_ : (g == 1) ? Wi_ : (g == 2) ? Wg_ : Wo_;
        for (int i = tid; i < 128 * 64; i += NTHR) {
            int p = i & 127, u = i >> 7;
            s_W[p * 256 + u * 4 + g] = Wp[(size_t)(sub * 64 + u) * P_ + p];
        }
    }
    for (int i = tid; i < 272; i += NTHR) { s_hA[i] = 0.f; s_hB[i] = 0.f; }
    const ull bfi = pack2(bf_[gu], bi_[gu]);
    const ull bgo = pack2(bg_[gu], bo_[gu]);
    __syncthreads();

    // preload pH row p1p into registers (64 floats)
    ull phr[32];
    {
        const ulonglong2* pr = (const ulonglong2*)&s_pH[p1p * 68];
#pragma unroll
        for (int i = 0; i < 16; i++) {
            ulonglong2 v = pr[i];
            phr[2*i] = v.x; phr[2*i+1] = v.y;
        }
    }

    float cA = 0.f, cB = 0.f, hAv = 0.f, hBv = 0.f;
    const size_t OUT_H = (size_t)T_ * BH_;

    unsigned int* flagA = &g_flags[(0 * NGRP + grp) * 32 + sub];
    unsigned int* flagB = &g_flags[(1 * NGRP + grp) * 32 + sub];
    const unsigned int* pollA = &g_flags[(0 * NGRP + grp) * 32];
    const unsigned int* pollB = &g_flags[(1 * NGRP + grp) * 32];

    // per-thread A-term rows: set A rows grp*8 + rh*2 +{0,1}; set B +4
    const int ra0 = grp * 8 + rh * 2;
    float aA0, aA1, aB0, aB1;
    aA0 = __ldcg(&g_A[(size_t)(ra0    ) * P_ + p1p]);
    aA1 = __ldcg(&g_A[(size_t)(ra0 + 1) * P_ + p1p]);
    aB0 = __ldcg(&g_A[(size_t)(ra0 + 4) * P_ + p1p]);
    aB1 = __ldcg(&g_A[(size_t)(ra0 + 5) * P_ + p1p]);

    // ============ macros for the four building blocks ============
#define PHASE1(SH, SLICE)                                                     \
    {                                                                         \
        const ulonglong2* h0 = (const ulonglong2*)((SH) + (rh*2+0)*68);       \
        const ulonglong2* h1 = (const ulonglong2*)((SH) + (rh*2+1)*68);       \
        ull a0=0ull,b0=0ull,a1=0ull,b1=0ull;                                  \
        _Pragma("unroll 4")                                                   \
        for (int jc = 0; jc < 16; jc++) {                                     \
            ulonglong2 hv0 = h0[jc], hv1 = h1[jc];                            \
            a0 = fma2(hv0.x, phr[2*jc],   a0);                                \
            b0 = fma2(hv0.y, phr[2*jc+1], b0);                                \
            a1 = fma2(hv1.x, phr[2*jc],   a1);                                \
            b1 = fma2(hv1.y, phr[2*jc+1], b1);                                \
        }                                                                     \
        float x0,x1,x2,x3,y0,y1,y2,y3;                                        \
        unpack2(a0,x0,x1); unpack2(b0,x2,x3);                                 \
        unpack2(a1,y0,y1); unpack2(b1,y2,y3);                                 \
        float2 pw = make_float2((x0+x1)+(x2+x3), (y0+y1)+(y2+y3));            \
        *(float2*)&(SLICE)[p1p*4 + rh*2] = pw;                                \
        if (tid < 32) {                                                       \
            int row = tid >> 3, seg = (tid & 7) * 8;                          \
            const float* hr = (SH) + row*68 + seg;                            \
            float ss = 0.f;                                                   \
            _Pragma("unroll")                                                 \
            for (int j = 0; j < 8; j++) ss += hr[j]*hr[j];                    \
            _Pragma("unroll")                                                 \
            for (int o = 4; o; o >>= 1)                                       \
                ss += __shfl_down_sync(0xffffffffu, ss, o, 8);                \
            if ((tid & 7) == 0) (SLICE)[512 + row] = ss;                      \
        }                                                                     \
    }

#define DETECT(POLL, TGT)                                                     \
    if (tid == 0) {                                                           \
        unsigned v0, v1, v2, v3, tg = (unsigned)(TGT);                        \
        do {                                                                  \
            asm volatile("ld.acquire.gpu.global.u32 %0,[%1];"                 \
                         : "=r"(v0) : "l"((POLL)+0) : "memory");              \
            asm volatile("ld.acquire.gpu.global.u32 %0,[%1];"                 \
                         : "=r"(v1) : "l"((POLL)+1) : "memory");              \
            asm volatile("ld.acquire.gpu.global.u32 %0,[%1];"                 \
                         : "=r"(v2) : "l"((POLL)+2) : "memory");              \
            asm volatile("ld.acquire.gpu.global.u32 %0,[%1];"                 \
                         : "=r"(v3) : "l"((POLL)+3) : "memory");              \
        } while (v0 < tg || v1 < tg || v2 < tg || v3 < tg);                   \
    }                                                                         \
    __syncthreads();

#define REDUCE_EXP(BASE, SK, A0, A1)                                          \
    {                                                                         \
        float2 u0 = __ldcg((const float2*)((BASE) + 0*SLICE_F + p1p*4 + rh*2));\
        float2 u1 = __ldcg((const float2*)((BASE) + 1*SLICE_F + p1p*4 + rh*2));\
        float2 u2 = __ldcg((const float2*)((BASE) + 2*SLICE_F + p1p*4 + rh*2));\
        float2 u3 = __ldcg((const float2*)((BASE) + 3*SLICE_F + p1p*4 + rh*2));\
        float2 q0 = __ldcg((const float2*)((BASE) + 0*SLICE_F + 512 + rh*2)); \
        float2 q1 = __ldcg((const float2*)((BASE) + 1*SLICE_F + 512 + rh*2)); \
        float2 q2 = __ldcg((const float2*)((BASE) + 2*SLICE_F + 512 + rh*2)); \
        float2 q3 = __ldcg((const float2*)((BASE) + 3*SLICE_F + 512 + rh*2)); \
        float d0 = (u0.x+u1.x)+(u2.x+u3.x);                                   \
        float d1 = (u0.y+u1.y)+(u2.y+u3.y);                                   \
        float h0 = (q0.x+q1.x)+(q2.x+q3.x);                                   \
        float h1 = (q0.y+q1.y)+(q2.y+q3.y);                                   \
        (SK)[(rh*2+0)*132 + p1p] = __expf(-((A0) + h0 - 2.f*d0));             \
        (SK)[(rh*2+1)*132 + p1p] = __expf(-((A1) + h1 - 2.f*d1));             \
    }

#define PHASE2(SK, SH, CC, HH, IDX, TT)                                       \
    {                                                                         \
        ull afi0 = bfi, ago0 = bgo, afi1 = 0ull, ago1 = 0ull;                 \
        const float* kr = (SK) + prow * 132;                                  \
        const float* wb = s_W + unit * 4;                                     \
        _Pragma("unroll 8")                                                   \
        for (int pc = 0; pc < 32; pc++) {                                     \
            float4 kq = *(const float4*)(kr + pc * 4);                        \
            ull k0 = pack2(kq.x, kq.x), k1 = pack2(kq.y, kq.y);               \
            ull k2 = pack2(kq.z, kq.z), k3 = pack2(kq.w, kq.w);               \
            ulonglong2 w0 = *(const ulonglong2*)(wb + (pc*4+0)*256);          \
            ulonglong2 w1 = *(const ulonglong2*)(wb + (pc*4+1)*256);          \
            ulonglong2 w2 = *(const ulonglong2*)(wb + (pc*4+2)*256);          \
            ulonglong2 w3 = *(const ulonglong2*)(wb + (pc*4+3)*256);          \
            afi0 = fma2(k0, w0.x, afi0); ago0 = fma2(k0, w0.y, ago0);         \
            afi1 = fma2(k1, w1.x, afi1); ago1 = fma2(k1, w1.y, ago1);         \
            afi0 = fma2(k2, w2.x, afi0); ago0 = fma2(k2, w2.y, ago0);         \
            afi1 = fma2(k3, w3.x, afi1); ago1 = fma2(k3, w3.y, ago1);         \
        }                                                                     \
        float vf0,vi0,vg0,vo0,vf1,vi1,vg1,vo1;                                \
        unpack2(afi0,vf0,vi0); unpack2(ago0,vg0,vo0);                         \
        unpack2(afi1,vf1,vi1); unpack2(ago1,vg1,vo1);                         \
        float vf = vf0+vf1, vi = vi0+vi1, vg = vg0+vg1, vo = vo0+vo1;         \
        float f = sigf(vf), ii = sigf(vi), gg = tanh_fast(vg), o = sigf(vo);  \
        (CC) = f * (CC) + ii * gg;                                            \
        (HH) = o * tanh_fast(CC);                                             \
        (SH)[prow * 68 + unit] = (HH);                                        \
        out[(size_t)(TT) * BH_ + (IDX)] = (HH);                               \
    }

#define FLAG_SET(FL, VAL)                                                     \
    if (tid == 0)                                                             \
        asm volatile("st.release.gpu.global.u32 [%0], %1;"                    \
                     :: "l"(FL), "r"((unsigned)(VAL)) : "memory");

    // slice base pointers
#define SLICE_PTR(BUF, SET) \
    (g_part + ((((size_t)(BUF) * NGRP + grp) * 2 + (SET)) * GBLK + sub) * SLICE_F)
#define RED_BASE(BUF, SET) \
    (g_part + ((((size_t)(BUF) * NGRP + grp) * 2 + (SET)) * GBLK) * SLICE_F)

    // ================= prologue: t = 0 (no exchange) =================
    {
        s_kA[(rh*2+0)*132 + p1p] = __expf(-aA0);
        s_kA[(rh*2+1)*132 + p1p] = __expf(-aA1);
        s_kB[(rh*2+0)*132 + p1p] = __expf(-aB0);
        s_kB[(rh*2+1)*132 + p1p] = __expf(-aB1);
        // prefetch A-terms for t=1
        size_t b1 = (size_t)1 * B_ * P_;
        aA0 = __ldcg(&g_A[b1 + (size_t)(ra0    ) * P_ + p1p]);
        aA1 = __ldcg(&g_A[b1 + (size_t)(ra0 + 1) * P_ + p1p]);
        aB0 = __ldcg(&g_A[b1 + (size_t)(ra0 + 4) * P_ + p1p]);
        aB1 = __ldcg(&g_A[b1 + (size_t)(ra0 + 5) * P_ + p1p]);
    }
    __syncthreads();
    PHASE2(s_kA, s_hA, cA, hAv, idxA, 0)
    PHASE2(s_kB, s_hB, cB, hBv, idxB, 0)
    __syncthreads();
    PHASE1(s_hA, SLICE_PTR(1, 0))
    PHASE1(s_hB, SLICE_PTR(1, 1))
    __syncthreads();
    FLAG_SET(flagA, 1)
    FLAG_SET(flagB, 1)

    // ================= main pipelined loop =================
#pragma unroll 1
    for (int t = 1; t < T_; t++) {
        const int buf = t & 1;
        const int tn  = (t + 1 < T_) ? (t + 1) : (T_ - 1);
        const size_t abase = (size_t)tn * B_ * P_;

        // ---------- set A ----------
        DETECT(pollA, t)
        REDUCE_EXP(RED_BASE(buf, 0), s_kA, aA0, aA1)
        aA0 = __ldcg(&g_A[abase + (size_t)(ra0    ) * P_ + p1p]);
        aA1 = __ldcg(&g_A[abase + (size_t)(ra0 + 1) * P_ + p1p]);
        __syncthreads();
        PHASE2(s_kA, s_hA, cA, hAv, idxA, t)
        __syncthreads();
        if (t < T_ - 1) {
            PHASE1(s_hA, SLICE_PTR(buf ^ 1, 0))
            __syncthreads();
            FLAG_SET(flagA, t + 1)
        }

        // ---------- set B ----------
        DETECT(pollB, t)
        REDUCE_EXP(RED_BASE(buf, 1), s_kB, aB0, aB1)
        aB0 = __ldcg(&g_A[abase + (size_t)(ra0 + 4) * P_ + p1p]);
        aB1 = __ldcg(&g_A[abase + (size_t)(ra0 + 5) * P_ + p1p]);
        __syncthreads();
        PHASE2(s_kB, s_hB, cB, hBv, idxB, t)
        __syncthreads();
        if (t < T_ - 1) {
            PHASE1(s_hB, SLICE_PTR(buf ^ 1, 1))
            __syncthreads();
            FLAG_SET(flagB, t + 1)
        }
    }

    // final hx / cx
    out[OUT_H + idxA] = hAv;
    out[OUT_H + BH_ + idxA] = cA;
    out[OUT_H + idxB] = hBv;
    out[OUT_H + BH_ + idxB] = cB;
}

// ---------------- launch ----------------------------------------------------
extern "C" void kernel_launch(void* const* d_in, const int* in_sizes, int n_in,
                              void* d_out, int out_size) {
    const float* x     = (const float*)d_in[0];
    const float* proto = (const float*)d_in[1];
    const float* Wf    = (const float*)d_in[2];
    const float* bf    = (const float*)d_in[3];
    const float* Wi    = (const float*)d_in[4];
    const float* bi    = (const float*)d_in[5];
    const float* Wg    = (const float*)d_in[6];
    const float* bg    = (const float*)d_in[7];
    const float* Wo    = (const float*)d_in[8];
    const float* bo    = (const float*)d_in[9];
    float* out = (float*)d_out;

    const int smem_bytes = SMEM_FLOATS * (int)sizeof(float);
    cudaFuncSetAttribute(qlstm_main, cudaFuncAttributeMaxDynamicSharedMemorySize,
                         smem_bytes);

    zero_flags_kernel<<<2, 1024>>>();
    xsq_kernel<<<M_ / 8, 256>>>(x);
    psum_kernel<<<1, 128>>>(proto);
    agemm_kernel<<<M_ / 64, 256>>>(x, proto);
    qlstm_main<<<NBLK, NTHR, smem_bytes>>>(proto, Wf, bf, Wi, bi, Wg, bg, Wo, bo, out);
}

// round 13
// speedup vs baseline: 1.4215x; 1.4215x over previous
#include <cuda_runtime.h>
#include <cstdint>

#define T_ 512
#define B_ 256
#define D_ 128
#define H_ 256
#define P_ 128
#define M_ (T_*B_)
#define NBLK 128
#define NTHR 256
#define BH_ (B_*H_)
#define NGRP 32           // 32 groups x 4 blocks, 8 batch rows each
#define GBLK 4
#define SLICE_F 528       // per (CTA,team) slice: 128p*4rows + 4 hsq + pad

typedef unsigned long long ull;

// ---------------- scratch ---------------------------------------------------
__device__ float g_A[(size_t)T_*B_*P_];          // precomputed x-part of distance
__device__ float g_xsq[M_];
__device__ float g_psum[P_];
__device__ float g_part[2*NGRP*2*GBLK*SLICE_F];  // [buf][grp][team][cta][slice]
__device__ unsigned int g_flags[NGRP*2*32];      // [grp][team][32]: words 0..3

// ---------------- f32x2 helpers --------------------------------------------
__device__ __forceinline__ ull pack2(float lo, float hi) {
    ull r; asm("mov.b64 %0, {%1, %2};" : "=l"(r) : "f"(lo), "f"(hi)); return r;
}
__device__ __forceinline__ void unpack2(ull v, float& lo, float& hi) {
    asm("mov.b64 {%0, %1}, %2;" : "=f"(lo), "=f"(hi) : "l"(v));
}
__device__ __forceinline__ ull fma2(ull a, ull b, ull c) {
    ull d; asm("fma.rn.f32x2 %0, %1, %2, %3;" : "=l"(d) : "l"(a), "l"(b), "l"(c));
    return d;
}
__device__ __forceinline__ float sigf(float x) {
    return __fdividef(1.f, 1.f + __expf(-x));
}
__device__ __forceinline__ float tanh_fast(float x) {
    float e = __expf(2.f * x);
    return 1.f - __fdividef(2.f, e + 1.f);
}
__device__ __forceinline__ void bar_named(int id) {
    asm volatile("bar.sync %0, 128;" :: "r"(id) : "memory");
}

// ---------------- precompute: row norms of x -------------------------------
__global__ void xsq_kernel(const float* __restrict__ x) {
    int warp = (blockIdx.x * blockDim.x + threadIdx.x) >> 5;
    int lane = threadIdx.x & 31;
    if (warp >= M_) return;
    const float* row = x + (size_t)warp * D_;
    float s = 0.f;
#pragma unroll
    for (int i = 0; i < 4; i++) { float v = row[lane + 32*i]; s += v*v; }
#pragma unroll
    for (int o = 16; o; o >>= 1) s += __shfl_down_sync(0xffffffffu, s, o);
    if (lane == 0) g_xsq[warp] = s;
}

// ---------------- precompute: full row norms of prototypes -----------------
__global__ void psum_kernel(const float* __restrict__ proto) {
    int p = threadIdx.x;
    if (p >= P_) return;
    const float* row = proto + (size_t)p * (D_ + H_);
    float s = 0.f;
    for (int i = 0; i < D_ + H_; i++) { float v = row[i]; s += v*v; }
    g_psum[p] = s;
}

// ---------------- precompute GEMM: A[t,b,p] = xsq + psum - 2*x.px ----------
__global__ void agemm_kernel(const float* __restrict__ x,
                             const float* __restrict__ proto) {
    __shared__ float sX[64][33];
    __shared__ float sP[32][132];
    const int tid = threadIdx.x;
    const int tx = tid & 31;
    const int ty = tid >> 5;
    const int m0 = blockIdx.x * 64;

    float acc[8][4];
#pragma unroll
    for (int r = 0; r < 8; r++)
#pragma unroll
        for (int q = 0; q < 4; q++) acc[r][q] = 0.f;

    for (int k0 = 0; k0 < D_; k0 += 32) {
#pragma unroll
        for (int i = 0; i < 8; i++) {
            int e = tid + i * 256;
            int r = e >> 5, c = e & 31;
            sX[r][c] = x[(size_t)(m0 + r) * D_ + k0 + c];
        }
#pragma unroll
        for (int i = 0; i < 16; i++) {
            int e = tid + i * 256;
            int p = e >> 5, c = e & 31;
            sP[c][p] = proto[(size_t)p * (D_ + H_) + k0 + c];
        }
        __syncthreads();
#pragma unroll
        for (int kc = 0; kc < 32; kc++) {
            float4 b4 = *(const float4*)&sP[kc][tx * 4];
#pragma unroll
            for (int r = 0; r < 8; r++) {
                float a = sX[ty * 8 + r][kc];
                acc[r][0] += a * b4.x; acc[r][1] += a * b4.y;
                acc[r][2] += a * b4.z; acc[r][3] += a * b4.w;
            }
        }
        __syncthreads();
    }
#pragma unroll
    for (int r = 0; r < 8; r++) {
        int row = m0 + ty * 8 + r;
        float xs = g_xsq[row];
        float4 o;
        o.x = xs + g_psum[tx*4+0] - 2.f * acc[r][0];
        o.y = xs + g_psum[tx*4+1] - 2.f * acc[r][1];
        o.z = xs + g_psum[tx*4+2] - 2.f * acc[r][2];
        o.w = xs + g_psum[tx*4+3] - 2.f * acc[r][3];
        *(float4*)&g_A[(size_t)row * P_ + tx * 4] = o;
    }
}

// ---------------- flag reset (graph replay determinism) --------------------
__global__ void zero_flags_kernel() {
    int i = blockIdx.x * blockDim.x + threadIdx.x;
    if (i < NGRP*2*32) g_flags[i] = 0;
}

// ---------------- main persistent recurrent kernel -------------------------
// smem floats: s_pH 128*68 | s_W 128*256 | s_h 8*68 | s_kT2 128*20
#define SMEM_FLOATS (8704 + 32768 + 544 + 2560)

__global__ void __launch_bounds__(NTHR, 1)
qlstm_main(const float* __restrict__ proto,
           const float* __restrict__ Wf_, const float* __restrict__ bf_,
           const float* __restrict__ Wi_, const float* __restrict__ bi_,
           const float* __restrict__ Wg_, const float* __restrict__ bg_,
           const float* __restrict__ Wo_, const float* __restrict__ bo_,
           float* __restrict__ out) {
    extern __shared__ float sm[];
    float* s_pH   = sm;                    // [128 p][68] own 64-j slice of protoH
    float* s_W    = s_pH + 128 * 68;       // [p][ul*4+gate], 256 cols
    float* s_h    = s_W + 128 * 256;       // [8 rows][68] own 64-j slice
    float* s_kT2  = s_h + 8 * 68;          // [p][row*2] duplicated k, pitch 20

    const int tid = threadIdx.x;
    const int bid = blockIdx.x;
    const int grp = bid >> 2;       // batch group 0..31 (8 rows)
    const int sub = bid & 3;        // j-chunk / unit-chunk (64 wide)
    const int tm  = tid >> 7;       // team 0: rows 0-3, team 1: rows 4-7
    const int tt  = tid & 127;      // thread-in-team
    const int barid = tm + 1;       // named barrier id

    // phase-1 / reduce / exp role: thread -> p = tt, 4 team rows
    // phase-2 role: warp-in-team covers 16 units x 2 row-pairs
    const int wt   = tt >> 5;                 // warp in team 0..3
    const int lane = tid & 31;
    const int unit = wt * 16 + (lane & 15);   // local unit 0..63
    const int pair = lane >> 4;               // 0..1
    const int row0 = tm * 4 + pair * 2;       // even row 0..7
    const int gu   = sub * 64 + unit;         // global unit
    const int idx0 = (grp * 8 + row0) * H_ + gu;
    const int idx1 = idx0 + H_;

    // ---- persistent SMEM fills ----
    for (int i = tid; i < 128 * 64; i += NTHR) {
        int p = i >> 6, j = i & 63;
        s_pH[p * 68 + j] = proto[(size_t)p * (D_ + H_) + D_ + sub * 64 + j];
    }
#pragma unroll
    for (int g = 0; g < 4; g++) {
        const float* Wp = (g == 0) ? Wf_ : (g == 1) ? Wi_ : (g == 2) ? Wg_ : Wo_;
        for (int i = tid; i < 128 * 64; i += NTHR) {
            int p = i & 127, u = i >> 7;
            s_W[p * 256 + u * 4 + g] = Wp[(size_t)(sub * 64 + u) * P_ + p];
        }
    }
    for (int i = tid; i < 8 * 68; i += NTHR) s_h[i] = 0.f;
    const ull bfi = pack2(bf_[gu], bi_[gu]);
    const ull bgo = pack2(bg_[gu], bo_[gu]);
    __syncthreads();

    // ---- preload this thread's pH row into registers (64 floats) ----
    ull phr[32];
    {
        const ulonglong2* pr = (const ulonglong2*)&s_pH[tt * 68];
#pragma unroll
        for (int i = 0; i < 16; i++) {
            ulonglong2 v = pr[i];
            phr[2*i] = v.x; phr[2*i+1] = v.y;
        }
    }

    float c0 = 0.f, c1 = 0.f, h0v = 0.f, h1v = 0.f;
    unsigned int* myflag = &g_flags[(grp * 2 + tm) * 32 + sub];
    const unsigned int* pollbase = &g_flags[(grp * 2 + tm) * 32];
    const size_t OUT_H = (size_t)T_ * BH_;

    // prefetch A(0) for this thread's (p=tt, 4 team rows)
    float a_cur[4];
#pragma unroll
    for (int r = 0; r < 4; r++)
        a_cur[r] = __ldcg(&g_A[(size_t)(grp * 8 + tm * 4 + r) * P_ + tt]);

#pragma unroll 1
    for (int t = 0; t < T_; t++) {
        const int buf = t & 1;
        float dsum[4] = {0.f, 0.f, 0.f, 0.f};
        float hh4[4]  = {0.f, 0.f, 0.f, 0.f};

        if (t > 0) {
            float* myslice = &g_part[((((size_t)buf * NGRP + grp) * 2 + tm)
                                      * GBLK + sub) * SLICE_F];
            // ===== phase 1: partial dots (pH in regs, h broadcast LDS) =====
            {
                const ulonglong2* hr0 = (const ulonglong2*)&s_h[(tm*4+0) * 68];
                const ulonglong2* hr1 = (const ulonglong2*)&s_h[(tm*4+1) * 68];
                const ulonglong2* hr2 = (const ulonglong2*)&s_h[(tm*4+2) * 68];
                const ulonglong2* hr3 = (const ulonglong2*)&s_h[(tm*4+3) * 68];
                ull aA[4], aB[4];
#pragma unroll
                for (int r = 0; r < 4; r++) { aA[r] = 0ull; aB[r] = 0ull; }
#pragma unroll 4
                for (int jc = 0; jc < 16; jc++) {
                    ulonglong2 h0 = hr0[jc], h1 = hr1[jc];
                    ulonglong2 h2 = hr2[jc], h3 = hr3[jc];
                    aA[0] = fma2(h0.x, phr[2*jc],   aA[0]);
                    aB[0] = fma2(h0.y, phr[2*jc+1], aB[0]);
                    aA[1] = fma2(h1.x, phr[2*jc],   aA[1]);
                    aB[1] = fma2(h1.y, phr[2*jc+1], aB[1]);
                    aA[2] = fma2(h2.x, phr[2*jc],   aA[2]);
                    aB[2] = fma2(h2.y, phr[2*jc+1], aB[2]);
                    aA[3] = fma2(h3.x, phr[2*jc],   aA[3]);
                    aB[3] = fma2(h3.y, phr[2*jc+1], aB[3]);
                }
                float4 pw;
                float* pwf = (float*)&pw;
#pragma unroll
                for (int r = 0; r < 4; r++) {
                    float x0, x1, x2, x3;
                    unpack2(aA[r], x0, x1);
                    unpack2(aB[r], x2, x3);
                    pwf[r] = (x0 + x1) + (x2 + x3);
                }
                *(float4*)&myslice[tt * 4] = pw;
            }
            // ===== partial |h|^2 (32 threads per team) -> slice tail =====
            if (tt < 32) {
                int row = tt >> 3, seg = (tt & 7) * 8;
                const float* hr = &s_h[(tm * 4 + row) * 68 + seg];
                float ss = 0.f;
#pragma unroll
                for (int j = 0; j < 8; j++) ss += hr[j] * hr[j];
#pragma unroll
                for (int o = 4; o; o >>= 1)
                    ss += __shfl_down_sync(0xffffffffu, ss, o, 8);
                if ((tt & 7) == 0)
                    myslice[512 + row] = ss;
            }
            // ===== team publish: release-store flag (no atomic hop) =====
            bar_named(barid);
            if (tt == 0)
                asm volatile("st.release.gpu.global.u32 [%0], %1;"
                             :: "l"(myflag), "r"((unsigned)t) : "memory");
            // ===== team wait: poll 4 flags on one line, MLP=4 =====
            if (tt == 0) {
                unsigned v0, v1, v2, v3, tg = (unsigned)t;
                do {
                    asm volatile("ld.acquire.gpu.global.u32 %0,[%1];"
                                 : "=r"(v0) : "l"(pollbase + 0) : "memory");
                    asm volatile("ld.acquire.gpu.global.u32 %0,[%1];"
                                 : "=r"(v1) : "l"(pollbase + 1) : "memory");
                    asm volatile("ld.acquire.gpu.global.u32 %0,[%1];"
                                 : "=r"(v2) : "l"(pollbase + 2) : "memory");
                    asm volatile("ld.acquire.gpu.global.u32 %0,[%1];"
                                 : "=r"(v3) : "l"(pollbase + 3) : "memory");
                } while (v0 < tg || v1 < tg || v2 < tg || v3 < tg);
            }
            bar_named(barid);

            // ===== fused reduce: 4 slices, partials + hsq, MLP=8 =====
            {
                const float* base = &g_part[((((size_t)buf * NGRP + grp) * 2 + tm)
                                             * GBLK) * SLICE_F];
                float4 u[GBLK], hq[GBLK];
#pragma unroll
                for (int s = 0; s < GBLK; s++) {
                    u[s]  = __ldcg((const float4*)(base + s * SLICE_F + tt * 4));
                    hq[s] = __ldcg((const float4*)(base + s * SLICE_F + 512));
                }
                dsum[0] = (u[0].x + u[1].x) + (u[2].x + u[3].x);
                dsum[1] = (u[0].y + u[1].y) + (u[2].y + u[3].y);
                dsum[2] = (u[0].z + u[1].z) + (u[2].z + u[3].z);
                dsum[3] = (u[0].w + u[1].w) + (u[2].w + u[3].w);
                hh4[0]  = (hq[0].x + hq[1].x) + (hq[2].x + hq[3].x);
                hh4[1]  = (hq[0].y + hq[1].y) + (hq[2].y + hq[3].y);
                hh4[2]  = (hq[0].z + hq[1].z) + (hq[2].z + hq[3].z);
                hh4[3]  = (hq[0].w + hq[1].w) + (hq[2].w + hq[3].w);
            }
        }

        // ===== assemble k, duplicated layout =====
        {
            float kv[4];
#pragma unroll
            for (int r = 0; r < 4; r++) {
                float d2 = (t > 0)
                    ? (a_cur[r] + hh4[r] - 2.f * dsum[r])
                    : a_cur[r];
                kv[r] = __expf(-d2);
            }
            float4* dst = (float4*)&s_kT2[tt * 20 + tm * 8];
            dst[0] = make_float4(kv[0], kv[0], kv[1], kv[1]);
            dst[1] = make_float4(kv[2], kv[2], kv[3], kv[3]);
        }
        // prefetch A(t+1) — latency hidden under the GEMM
        {
            int tn = (t + 1 < T_) ? (t + 1) : (T_ - 1);
#pragma unroll
            for (int r = 0; r < 4; r++)
                a_cur[r] = __ldcg(&g_A[(size_t)tn * B_ * P_ +
                                       (size_t)(grp * 8 + tm * 4 + r) * P_ + tt]);
        }
        bar_named(barid);   // team's kT2 half visible to team

        // ===== phase 2: gate GEMM + state update (team half) =====
        {
            ull afi0 = bfi, ago0 = bgo, afi1 = bfi, ago1 = bgo;
            const float* kbase = &s_kT2[row0 * 2];
            const float* wbase = &s_W[unit * 4];
#pragma unroll 8
            for (int p = 0; p < 128; p++) {
                ulonglong2 w2 = *(const ulonglong2*)(wbase + p * 256);
                ulonglong2 kk = *(const ulonglong2*)(kbase + p * 20);
                afi0 = fma2(kk.x, w2.x, afi0);
                ago0 = fma2(kk.x, w2.y, ago0);
                afi1 = fma2(kk.y, w2.x, afi1);
                ago1 = fma2(kk.y, w2.y, ago1);
            }
            float vf, vi, vg, vo;
            unpack2(afi0, vf, vi); unpack2(ago0, vg, vo);
            {
                float f = sigf(vf), ii = sigf(vi), gg = tanh_fast(vg), o = sigf(vo);
                c0 = f * c0 + ii * gg;
                h0v = o * tanh_fast(c0);
                s_h[row0 * 68 + unit] = h0v;
            }
            unpack2(afi1, vf, vi); unpack2(ago1, vg, vo);
            {
                float f = sigf(vf), ii = sigf(vi), gg = tanh_fast(vg), o = sigf(vo);
                c1 = f * c1 + ii * gg;
                h1v = o * tanh_fast(c1);
                s_h[(row0 + 1) * 68 + unit] = h1v;
            }
            out[(size_t)t * BH_ + idx0] = h0v;
            out[(size_t)t * BH_ + idx1] = h1v;
        }
        bar_named(barid);   // team's h visible before next phase1
    }

    // final hx / cx
    out[OUT_H + idx0] = h0v;
    out[OUT_H + BH_ + idx0] = c0;
    out[OUT_H + idx1] = h1v;
    out[OUT_H + BH_ + idx1] = c1;
}

// ---------------- launch ----------------------------------------------------
extern "C" void kernel_launch(void* const* d_in, const int* in_sizes, int n_in,
                              void* d_out, int out_size) {
    const float* x     = (const float*)d_in[0];
    const float* proto = (const float*)d_in[1];
    const float* Wf    = (const float*)d_in[2];
    const float* bf    = (const float*)d_in[3];
    const float* Wi    = (const float*)d_in[4];
    const float* bi    = (const float*)d_in[5];
    const float* Wg    = (const float*)d_in[6];
    const float* bg    = (const float*)d_in[7];
    const float* Wo    = (const float*)d_in[8];
    const float* bo    = (const float*)d_in[9];
    float* out = (float*)d_out;

    const int smem_bytes = SMEM_FLOATS * (int)sizeof(float);
    cudaFuncSetAttribute(qlstm_main, cudaFuncAttributeMaxDynamicSharedMemorySize,
                         smem_bytes);

    zero_flags_kernel<<<2, 1024>>>();
    xsq_kernel<<<M_ / 8, 256>>>(x);
    psum_kernel<<<1, 128>>>(proto);
    agemm_kernel<<<M_ / 64, 256>>>(x, proto);
    qlstm_main<<<NBLK, NTHR, smem_bytes>>>(proto, Wf, bf, Wi, bi, Wg, bg, Wo, bo, out);
}

// round 14
// speedup vs baseline: 1.6338x; 1.1494x over previous
#include <cuda_runtime.h>
#include <cstdint>

#define T_ 512
#define B_ 256
#define D_ 128
#define H_ 256
#define P_ 128
#define M_ (T_*B_)
#define NBLK 128
#define NTHR 256
#define BH_ (B_*H_)
#define NGRP 32           // 32 groups x 4 blocks, 8 batch rows each
#define GBLK 4
#define SLICE_F 1040      // per-slice floats: 128p*8rows + 8 hsq + pad (16B mult)

typedef unsigned long long ull;

// ---------------- scratch ---------------------------------------------------
__device__ float g_A[(size_t)T_*B_*P_];          // precomputed x-part of distance
__device__ float g_xsq[M_];
__device__ float g_psum[P_];
__device__ float g_part[2*NGRP*GBLK*SLICE_F];    // double-buffered partial dots+hsq
__device__ unsigned int g_cnt[NGRP*32];          // 1 barrier counter per group

// ---------------- f32x2 helpers --------------------------------------------
__device__ __forceinline__ ull pack2(float lo, float hi) {
    ull r; asm("mov.b64 %0, {%1, %2};" : "=l"(r) : "f"(lo), "f"(hi)); return r;
}
__device__ __forceinline__ void unpack2(ull v, float& lo, float& hi) {
    asm("mov.b64 {%0, %1}, %2;" : "=f"(lo), "=f"(hi) : "l"(v));
}
__device__ __forceinline__ ull fma2(ull a, ull b, ull c) {
    ull d; asm("fma.rn.f32x2 %0, %1, %2, %3;" : "=l"(d) : "l"(a), "l"(b), "l"(c));
    return d;
}
__device__ __forceinline__ float sigf(float x) {
    return __fdividef(1.f, 1.f + __expf(-x));
}
__device__ __forceinline__ float tanh_fast(float x) {
    float e = __expf(2.f * x);
    return 1.f - __fdividef(2.f, e + 1.f);
}

// ---------------- precompute: row norms of x -------------------------------
__global__ void xsq_kernel(const float* __restrict__ x) {
    int warp = (blockIdx.x * blockDim.x + threadIdx.x) >> 5;
    int lane = threadIdx.x & 31;
    if (warp >= M_) return;
    const float* row = x + (size_t)warp * D_;
    float s = 0.f;
#pragma unroll
    for (int i = 0; i < 4; i++) { float v = row[lane + 32*i]; s += v*v; }
#pragma unroll
    for (int o = 16; o; o >>= 1) s += __shfl_down_sync(0xffffffffu, s, o);
    if (lane == 0) g_xsq[warp] = s;
}

// ---------------- precompute: full row norms of prototypes -----------------
__global__ void psum_kernel(const float* __restrict__ proto) {
    int p = threadIdx.x;
    if (p >= P_) return;
    const float* row = proto + (size_t)p * (D_ + H_);
    float s = 0.f;
    for (int i = 0; i < D_ + H_; i++) { float v = row[i]; s += v*v; }
    g_psum[p] = s;
}

// ---------------- precompute GEMM: A[t,b,p] = xsq + psum - 2*x.px ----------
__global__ void agemm_kernel(const float* __restrict__ x,
                             const float* __restrict__ proto) {
    __shared__ float sX[64][33];
    __shared__ float sP[32][132];
    const int tid = threadIdx.x;
    const int tx = tid & 31;
    const int ty = tid >> 5;
    const int m0 = blockIdx.x * 64;

    float acc[8][4];
#pragma unroll
    for (int r = 0; r < 8; r++)
#pragma unroll
        for (int q = 0; q < 4; q++) acc[r][q] = 0.f;

    for (int k0 = 0; k0 < D_; k0 += 32) {
#pragma unroll
        for (int i = 0; i < 8; i++) {
            int e = tid + i * 256;
            int r = e >> 5, c = e & 31;
            sX[r][c] = x[(size_t)(m0 + r) * D_ + k0 + c];
        }
#pragma unroll
        for (int i = 0; i < 16; i++) {
            int e = tid + i * 256;
            int p = e >> 5, c = e & 31;
            sP[c][p] = proto[(size_t)p * (D_ + H_) + k0 + c];
        }
        __syncthreads();
#pragma unroll
        for (int kc = 0; kc < 32; kc++) {
            float4 b4 = *(const float4*)&sP[kc][tx * 4];
#pragma unroll
            for (int r = 0; r < 8; r++) {
                float a = sX[ty * 8 + r][kc];
                acc[r][0] += a * b4.x; acc[r][1] += a * b4.y;
                acc[r][2] += a * b4.z; acc[r][3] += a * b4.w;
            }
        }
        __syncthreads();
    }
#pragma unroll
    for (int r = 0; r < 8; r++) {
        int row = m0 + ty * 8 + r;
        float xs = g_xsq[row];
        float4 o;
        o.x = xs + g_psum[tx*4+0] - 2.f * acc[r][0];
        o.y = xs + g_psum[tx*4+1] - 2.f * acc[r][1];
        o.z = xs + g_psum[tx*4+2] - 2.f * acc[r][2];
        o.w = xs + g_psum[tx*4+3] - 2.f * acc[r][3];
        *(float4*)&g_A[(size_t)row * P_ + tx * 4] = o;
    }
}

// ---------------- counter reset (graph replay determinism) -----------------
__global__ void zero_cnt_kernel() {
    int i = threadIdx.x;
    if (i < NGRP*32) g_cnt[i] = 0;
}

// ---------------- split group barrier --------------------------------------
__device__ __forceinline__ void bar_arrive(unsigned int* cnt) {
    __syncthreads();
    if (threadIdx.x == 0)
        asm volatile("red.release.gpu.global.add.u32 [%0], 1;"
                     :: "l"(cnt) : "memory");
}
__device__ __forceinline__ void bar_wait(unsigned int* cnt, unsigned int target) {
    if (threadIdx.x == 0) {
        unsigned int v;
        do {
            asm volatile("ld.acquire.gpu.global.u32 %0, [%1];"
                         : "=r"(v) : "l"(cnt) : "memory");
        } while (v < target);
    }
    __syncthreads();
}

// ---------------- main persistent recurrent kernel -------------------------
// smem floats: s_pH 128*68 | s_W 128*256 | s_h 8*68 | s_kT2 128*20
#define SMEM_FLOATS (8704 + 32768 + 544 + 2560)

__global__ void __launch_bounds__(NTHR, 1)
qlstm_main(const float* __restrict__ proto,
           const float* __restrict__ Wf_, const float* __restrict__ bf_,
           const float* __restrict__ Wi_, const float* __restrict__ bi_,
           const float* __restrict__ Wg_, const float* __restrict__ bg_,
           const float* __restrict__ Wo_, const float* __restrict__ bo_,
           float* __restrict__ out) {
    extern __shared__ float sm[];
    float* s_pH   = sm;                    // [128 p][68] own 64-j slice of protoH
    float* s_W    = s_pH + 128 * 68;       // [p][ul*4+gate], 256 cols
    float* s_h    = s_W + 128 * 256;       // [8 rows][68] own 64-j slice (local!)
    float* s_kT2  = s_h + 8 * 68;          // [p][row*2] duplicated k, pitch 20

    const int tid = threadIdx.x;
    const int bid = blockIdx.x;
    const int grp = bid >> 2;   // batch group 0..31 (8 rows each)
    const int sub = bid & 3;    // j-chunk / unit-chunk (64 wide)

    // phase-1 / reduce mapping: thread -> (p, 4 rows)
    const int p1p = tid >> 1;          // 0..127
    const int rh4 = tid & 1;           // rows rh4*4 .. rh4*4+3
    // phase-2 mapping: warp = 8 local units x 4 row-pairs
    const int w    = tid >> 5;
    const int lane = tid & 31;
    const int ul   = w * 8 + (lane & 7);     // local unit 0..63
    const int rp   = lane >> 3;              // 0..3
    const int row0 = rp * 2;                 // even row
    const int gu   = sub * 64 + ul;          // global unit
    const int idx0 = (grp * 8 + row0) * H_ + gu;
    const int idx1 = idx0 + H_;

    // ---- persistent SMEM fills ----
    for (int i = tid; i < 128 * 64; i += NTHR) {
        int p = i >> 6, j = i & 63;
        s_pH[p * 68 + j] = proto[(size_t)p * (D_ + H_) + D_ + sub * 64 + j];
    }
#pragma unroll
    for (int g = 0; g < 4; g++) {
        const float* Wp = (g == 0) ? Wf_ : (g == 1) ? Wi_ : (g == 2) ? Wg_ : Wo_;
        for (int i = tid; i < 128 * 64; i += NTHR) {
            int p = i & 127, u = i >> 7;
            s_W[p * 256 + u * 4 + g] = Wp[(size_t)(sub * 64 + u) * P_ + p];
        }
    }
    for (int i = tid; i < 8 * 68; i += NTHR) s_h[i] = 0.f;
    const ull bfi = pack2(bf_[gu], bi_[gu]);
    const ull bgo = pack2(bg_[gu], bo_[gu]);
    __syncthreads();

    // ---- preload this thread's pH row (p = p1p) into registers ----
    ull phr[32];
    {
        const ulonglong2* pr = (const ulonglong2*)&s_pH[p1p * 68];
#pragma unroll
        for (int i = 0; i < 16; i++) {
            ulonglong2 v = pr[i];
            phr[2*i] = v.x; phr[2*i+1] = v.y;
        }
    }

    float c0 = 0.f, c1 = 0.f, h0v = 0.f, h1v = 0.f;

    unsigned int* cnt = &g_cnt[grp * 32];
    const size_t OUT_H = (size_t)T_ * BH_;

    // prefetch A(0) for this thread's (p, 4 rows)
    float a_cur[4];
#pragma unroll
    for (int r = 0; r < 4; r++)
        a_cur[r] = __ldcg(&g_A[(size_t)(grp * 8 + rh4 * 4 + r) * P_ + p1p]);

#pragma unroll 1
    for (int t = 0; t < T_; t++) {
        const int buf = t & 1;
        float dsum[4] = {0.f, 0.f, 0.f, 0.f};
        float hh4[4]  = {0.f, 0.f, 0.f, 0.f};

        if (t > 0) {
            float* myslice = &g_part[(((size_t)buf * NGRP + grp) * GBLK + sub)
                                     * SLICE_F];
            // ===== phase 1: partial dots (pH in regs, h broadcast LDS) =====
            {
                ull accA[4], accB[4];
#pragma unroll
                for (int r = 0; r < 4; r++) { accA[r] = 0ull; accB[r] = 0ull; }
#pragma unroll 4
                for (int jc = 0; jc < 16; jc++) {
                    ull pvx = phr[2*jc], pvy = phr[2*jc+1];
#pragma unroll
                    for (int r = 0; r < 4; r++) {
                        ulonglong2 hv = *(const ulonglong2*)
                            &s_h[(rh4 * 4 + r) * 68 + jc * 4];
                        accA[r] = fma2(hv.x, pvx, accA[r]);
                        accB[r] = fma2(hv.y, pvy, accB[r]);
                    }
                }
                float4 pw;
                float* pwf = (float*)&pw;
#pragma unroll
                for (int r = 0; r < 4; r++) {
                    float x0, x1, x2, x3;
                    unpack2(accA[r], x0, x1);
                    unpack2(accB[r], x2, x3);
                    pwf[r] = (x0 + x1) + (x2 + x3);
                }
                *(float4*)&myslice[p1p * 8 + rh4 * 4] = pw;
            }
            // ===== partial |h|^2 over own 64 j -> slice tail =====
            if (tid < 64) {
                int row = tid >> 3, seg = (tid & 7) * 8;
                const float* hr = &s_h[row * 68 + seg];
                float ss = 0.f;
#pragma unroll
                for (int j = 0; j < 8; j++) ss += hr[j] * hr[j];
#pragma unroll
                for (int o = 4; o; o >>= 1)
                    ss += __shfl_down_sync(0xffffffffu, ss, o, 8);
                if ((tid & 7) == 0)
                    myslice[1024 + row] = ss;
            }
            bar_arrive(cnt);
            bar_wait(cnt, 4u * (unsigned)t);

            // ===== fused reduce: partials + hsq in one MLP=8 LDG batch =====
            {
                const float* base =
                    &g_part[(((size_t)buf * NGRP + grp) * GBLK) * SLICE_F];
                float4 u[GBLK], hq[GBLK];
#pragma unroll
                for (int s = 0; s < GBLK; s++) {
                    u[s]  = __ldcg((const float4*)(base + s * SLICE_F
                                                   + p1p * 8 + rh4 * 4));
                    hq[s] = __ldcg((const float4*)(base + s * SLICE_F
                                                   + 1024 + rh4 * 4));
                }
                dsum[0] = (u[0].x + u[1].x) + (u[2].x + u[3].x);
                dsum[1] = (u[0].y + u[1].y) + (u[2].y + u[3].y);
                dsum[2] = (u[0].z + u[1].z) + (u[2].z + u[3].z);
                dsum[3] = (u[0].w + u[1].w) + (u[2].w + u[3].w);
                hh4[0]  = (hq[0].x + hq[1].x) + (hq[2].x + hq[3].x);
                hh4[1]  = (hq[0].y + hq[1].y) + (hq[2].y + hq[3].y);
                hh4[2]  = (hq[0].z + hq[1].z) + (hq[2].z + hq[3].z);
                hh4[3]  = (hq[0].w + hq[1].w) + (hq[2].w + hq[3].w);
            }
        }

        // ===== assemble k and write duplicated layout (no staging sync) =====
        {
            float kv[4];
#pragma unroll
            for (int r = 0; r < 4; r++) {
                float d2 = (t > 0)
                    ? (a_cur[r] + hh4[r] - 2.f * dsum[r])
                    : a_cur[r];
                kv[r] = __expf(-d2);
            }
            float4* dst = (float4*)&s_kT2[p1p * 20 + rh4 * 8];
            dst[0] = make_float4(kv[0], kv[0], kv[1], kv[1]);
            dst[1] = make_float4(kv[2], kv[2], kv[3], kv[3]);
        }
        // prefetch A(t+1) — latency hidden under the GEMM
        {
            int tn = (t + 1 < T_) ? (t + 1) : (T_ - 1);
#pragma unroll
            for (int r = 0; r < 4; r++)
                a_cur[r] = __ldcg(&g_A[(size_t)tn * B_ * P_ +
                                       (size_t)(grp * 8 + rh4 * 4 + r) * P_ + p1p]);
        }
        __syncthreads();

        // ===== phase 2: gate GEMM + state update (h stays local) =====
        {
            ull afi0 = bfi, ago0 = bgo, afi1 = bfi, ago1 = bgo;
            const float* kbase = &s_kT2[row0 * 2];
            const float* wbase = &s_W[ul * 4];
#pragma unroll 8
            for (int p = 0; p < 128; p++) {
                ulonglong2 w2 = *(const ulonglong2*)(wbase + p * 256);
                ulonglong2 kk = *(const ulonglong2*)(kbase + p * 20);
                afi0 = fma2(kk.x, w2.x, afi0);
                ago0 = fma2(kk.x, w2.y, ago0);
                afi1 = fma2(kk.y, w2.x, afi1);
                ago1 = fma2(kk.y, w2.y, ago1);
            }
            float vf, vi, vg, vo;
            unpack2(afi0, vf, vi); unpack2(ago0, vg, vo);
            {
                float f = sigf(vf), ii = sigf(vi), gg = tanh_fast(vg), o = sigf(vo);
                c0 = f * c0 + ii * gg;
                h0v = o * tanh_fast(c0);
                s_h[row0 * 68 + ul] = h0v;
            }
            unpack2(afi1, vf, vi); unpack2(ago1, vg, vo);
            {
                float f = sigf(vf), ii = sigf(vi), gg = tanh_fast(vg), o = sigf(vo);
                c1 = f * c1 + ii * gg;
                h1v = o * tanh_fast(c1);
                s_h[(row0 + 1) * 68 + ul] = h1v;
            }
            out[(size_t)t * BH_ + idx0] = h0v;
            out[(size_t)t * BH_ + idx1] = h1v;
        }
        __syncthreads();   // h complete before next phase1 reads s_h
    }

    // final hx / cx
    out[OUT_H + idx0] = h0v;
    out[OUT_H + BH_ + idx0] = c0;
    out[OUT_H + idx1] = h1v;
    out[OUT_H + BH_ + idx1] = c1;
}

// ---------------- launch ----------------------------------------------------
extern "C" void kernel_launch(void* const* d_in, const int* in_sizes, int n_in,
                              void* d_out, int out_size) {
    const float* x     = (const float*)d_in[0];
    const float* proto = (const float*)d_in[1];
    const float* Wf    = (const float*)d_in[2];
    const float* bf    = (const float*)d_in[3];
    const float* Wi    = (const float*)d_in[4];
    const float* bi    = (const float*)d_in[5];
    const float* Wg    = (const float*)d_in[6];
    const float* bg    = (const float*)d_in[7];
    const float* Wo    = (const float*)d_in[8];
    const float* bo    = (const float*)d_in[9];
    float* out = (float*)d_out;

    const int smem_bytes = SMEM_FLOATS * (int)sizeof(float);
    cudaFuncSetAttribute(qlstm_main, cudaFuncAttributeMaxDynamicSharedMemorySize,
                         smem_bytes);

    zero_cnt_kernel<<<1, 1024>>>();
    xsq_kernel<<<M_ / 8, 256>>>(x);
    psum_kernel<<<1, 128>>>(proto);
    agemm_kernel<<<M_ / 64, 256>>>(x, proto);
    qlstm_main<<<NBLK, NTHR, smem_bytes>>>(proto, Wf, bf, Wi, bi, Wg, bg, Wo, bo, out);
}

// round 15
// speedup vs baseline: 1.6556x; 1.0133x over previous
#include <cuda_runtime.h>
#include <cstdint>

#define T_ 512
#define B_ 256
#define D_ 128
#define H_ 256
#define P_ 128
#define M_ (T_*B_)
#define NBLK 128
#define NTHR 256
#define BH_ (B_*H_)
#define NGRP 32           // 32 groups x 4 blocks, 8 batch rows each
#define GBLK 4
#define SLICE_F 528       // per (CTA,team) slice: 128p*4rows + 4 hsq + pad

typedef unsigned long long ull;

// ---------------- scratch ---------------------------------------------------
__device__ float g_A[(size_t)T_*B_*P_];          // precomputed x-part of distance
__device__ float g_xsq[M_];
__device__ float g_psum[P_];
__device__ float g_part[2*NGRP*2*GBLK*SLICE_F];  // [buf][grp][team][cta][slice]
__device__ unsigned int g_cnt[NGRP*2*32];        // counter per (group, team)

// ---------------- f32x2 helpers --------------------------------------------
__device__ __forceinline__ ull pack2(float lo, float hi) {
    ull r; asm("mov.b64 %0, {%1, %2};" : "=l"(r) : "f"(lo), "f"(hi)); return r;
}
__device__ __forceinline__ void unpack2(ull v, float& lo, float& hi) {
    asm("mov.b64 {%0, %1}, %2;" : "=f"(lo), "=f"(hi) : "l"(v));
}
__device__ __forceinline__ ull fma2(ull a, ull b, ull c) {
    ull d; asm("fma.rn.f32x2 %0, %1, %2, %3;" : "=l"(d) : "l"(a), "l"(b), "l"(c));
    return d;
}
__device__ __forceinline__ float sigf(float x) {
    return __fdividef(1.f, 1.f + __expf(-x));
}
__device__ __forceinline__ float tanh_fast(float x) {
    float e = __expf(2.f * x);
    return 1.f - __fdividef(2.f, e + 1.f);
}
__device__ __forceinline__ void bar_named(int id) {
    asm volatile("bar.sync %0, 128;" :: "r"(id) : "memory");
}

// ---------------- precompute: row norms of x -------------------------------
__global__ void xsq_kernel(const float* __restrict__ x) {
    int warp = (blockIdx.x * blockDim.x + threadIdx.x) >> 5;
    int lane = threadIdx.x & 31;
    if (warp >= M_) return;
    const float* row = x + (size_t)warp * D_;
    float s = 0.f;
#pragma unroll
    for (int i = 0; i < 4; i++) { float v = row[lane + 32*i]; s += v*v; }
#pragma unroll
    for (int o = 16; o; o >>= 1) s += __shfl_down_sync(0xffffffffu, s, o);
    if (lane == 0) g_xsq[warp] = s;
}

// ---------------- precompute: full row norms of prototypes -----------------
__global__ void psum_kernel(const float* __restrict__ proto) {
    int p = threadIdx.x;
    if (p >= P_) return;
    const float* row = proto + (size_t)p * (D_ + H_);
    float s = 0.f;
    for (int i = 0; i < D_ + H_; i++) { float v = row[i]; s += v*v; }
    g_psum[p] = s;
}

// ---------------- precompute GEMM: A[t,b,p] = xsq + psum - 2*x.px ----------
__global__ void agemm_kernel(const float* __restrict__ x,
                             const float* __restrict__ proto) {
    __shared__ float sX[64][33];
    __shared__ float sP[32][132];
    const int tid = threadIdx.x;
    const int tx = tid & 31;
    const int ty = tid >> 5;
    const int m0 = blockIdx.x * 64;

    float acc[8][4];
#pragma unroll
    for (int r = 0; r < 8; r++)
#pragma unroll
        for (int q = 0; q < 4; q++) acc[r][q] = 0.f;

    for (int k0 = 0; k0 < D_; k0 += 32) {
#pragma unroll
        for (int i = 0; i < 8; i++) {
            int e = tid + i * 256;
            int r = e >> 5, c = e & 31;
            sX[r][c] = x[(size_t)(m0 + r) * D_ + k0 + c];
        }
#pragma unroll
        for (int i = 0; i < 16; i++) {
            int e = tid + i * 256;
            int p = e >> 5, c = e & 31;
            sP[c][p] = proto[(size_t)p * (D_ + H_) + k0 + c];
        }
        __syncthreads();
#pragma unroll
        for (int kc = 0; kc < 32; kc++) {
            float4 b4 = *(const float4*)&sP[kc][tx * 4];
#pragma unroll
            for (int r = 0; r < 8; r++) {
                float a = sX[ty * 8 + r][kc];
                acc[r][0] += a * b4.x; acc[r][1] += a * b4.y;
                acc[r][2] += a * b4.z; acc[r][3] += a * b4.w;
            }
        }
        __syncthreads();
    }
#pragma unroll
    for (int r = 0; r < 8; r++) {
        int row = m0 + ty * 8 + r;
        float xs = g_xsq[row];
        float4 o;
        o.x = xs + g_psum[tx*4+0] - 2.f * acc[r][0];
        o.y = xs + g_psum[tx*4+1] - 2.f * acc[r][1];
        o.z = xs + g_psum[tx*4+2] - 2.f * acc[r][2];
        o.w = xs + g_psum[tx*4+3] - 2.f * acc[r][3];
        *(float4*)&g_A[(size_t)row * P_ + tx * 4] = o;
    }
}

// ---------------- counter reset (graph replay determinism) -----------------
__global__ void zero_cnt_kernel() {
    int i = blockIdx.x * blockDim.x + threadIdx.x;
    if (i < NGRP*2*32) g_cnt[i] = 0;
}

// ---------------- main persistent recurrent kernel -------------------------
// smem floats: s_pH 128*68 | s_W 128*256 | s_h 8*68 | s_kT2 128*20
#define SMEM_FLOATS (8704 + 32768 + 544 + 2560)

__global__ void __launch_bounds__(NTHR, 1)
qlstm_main(const float* __restrict__ proto,
           const float* __restrict__ Wf_, const float* __restrict__ bf_,
           const float* __restrict__ Wi_, const float* __restrict__ bi_,
           const float* __restrict__ Wg_, const float* __restrict__ bg_,
           const float* __restrict__ Wo_, const float* __restrict__ bo_,
           float* __restrict__ out) {
    extern __shared__ float sm[];
    float* s_pH   = sm;                    // [128 p][68] own 64-j slice of protoH
    float* s_W    = s_pH + 128 * 68;       // [p][ul*4+gate], 256 cols
    float* s_h    = s_W + 128 * 256;       // [8 rows][68] own 64-j slice
    float* s_kT2  = s_h + 8 * 68;          // [p][row*2] duplicated k, pitch 20

    const int tid = threadIdx.x;
    const int bid = blockIdx.x;
    const int grp = bid >> 2;       // batch group 0..31 (8 rows)
    const int sub = bid & 3;        // j-chunk / unit-chunk (64 wide)
    const int tm  = tid >> 7;       // team 0: rows 0-3, team 1: rows 4-7
    const int tt  = tid & 127;      // thread-in-team
    const int barid = tm + 1;       // named barrier id

    // phase-1 / reduce / exp role: thread -> p = tt, 4 team rows
    // phase-2 role: warp-in-team covers 16 units x 2 row-pairs
    const int wt   = tt >> 5;                 // warp in team 0..3
    const int lane = tid & 31;
    const int unit = wt * 16 + (lane & 15);   // local unit 0..63
    const int pair = lane >> 4;               // 0..1
    const int row0 = tm * 4 + pair * 2;       // even row 0..7
    const int gu   = sub * 64 + unit;         // global unit
    const int idx0 = (grp * 8 + row0) * H_ + gu;
    const int idx1 = idx0 + H_;

    // ---- persistent SMEM fills ----
    for (int i = tid; i < 128 * 64; i += NTHR) {
        int p = i >> 6, j = i & 63;
        s_pH[p * 68 + j] = proto[(size_t)p * (D_ + H_) + D_ + sub * 64 + j];
    }
#pragma unroll
    for (int g = 0; g < 4; g++) {
        const float* Wp = (g == 0) ? Wf_ : (g == 1) ? Wi_ : (g == 2) ? Wg_ : Wo_;
        for (int i = tid; i < 128 * 64; i += NTHR) {
            int p = i & 127, u = i >> 7;
            s_W[p * 256 + u * 4 + g] = Wp[(size_t)(sub * 64 + u) * P_ + p];
        }
    }
    for (int i = tid; i < 8 * 68; i += NTHR) s_h[i] = 0.f;
    const ull bfi = pack2(bf_[gu], bi_[gu]);
    const ull bgo = pack2(bg_[gu], bo_[gu]);
    __syncthreads();

    // ---- preload this thread's pH row into registers (64 floats) ----
    ull phr[32];
    {
        const ulonglong2* pr = (const ulonglong2*)&s_pH[tt * 68];
#pragma unroll
        for (int i = 0; i < 16; i++) {
            ulonglong2 v = pr[i];
            phr[2*i] = v.x; phr[2*i+1] = v.y;
        }
    }

    float c0 = 0.f, c1 = 0.f, h0v = 0.f, h1v = 0.f;
    unsigned int* cnt = &g_cnt[(grp * 2 + tm) * 32];
    const size_t OUT_H = (size_t)T_ * BH_;

    // prefetch A(0) for this thread's (p=tt, 4 team rows)
    float a_cur[4];
#pragma unroll
    for (int r = 0; r < 4; r++)
        a_cur[r] = __ldcg(&g_A[(size_t)(grp * 8 + tm * 4 + r) * P_ + tt]);

#pragma unroll 1
    for (int t = 0; t < T_; t++) {
        const int buf = t & 1;
        float dsum[4] = {0.f, 0.f, 0.f, 0.f};
        float hh4[4]  = {0.f, 0.f, 0.f, 0.f};

        if (t > 0) {
            float* myslice = &g_part[((((size_t)buf * NGRP + grp) * 2 + tm)
                                      * GBLK + sub) * SLICE_F];
            // ===== phase 1: partial dots (pH in regs, h broadcast LDS) =====
            {
                const ulonglong2* hr0 = (const ulonglong2*)&s_h[(tm*4+0) * 68];
                const ulonglong2* hr1 = (const ulonglong2*)&s_h[(tm*4+1) * 68];
                const ulonglong2* hr2 = (const ulonglong2*)&s_h[(tm*4+2) * 68];
                const ulonglong2* hr3 = (const ulonglong2*)&s_h[(tm*4+3) * 68];
                ull aA[4], aB[4];
#pragma unroll
                for (int r = 0; r < 4; r++) { aA[r] = 0ull; aB[r] = 0ull; }
#pragma unroll 4
                for (int jc = 0; jc < 16; jc++) {
                    ulonglong2 h0 = hr0[jc], h1 = hr1[jc];
                    ulonglong2 h2 = hr2[jc], h3 = hr3[jc];
                    aA[0] = fma2(h0.x, phr[2*jc],   aA[0]);
                    aB[0] = fma2(h0.y, phr[2*jc+1], aB[0]);
                    aA[1] = fma2(h1.x, phr[2*jc],   aA[1]);
                    aB[1] = fma2(h1.y, phr[2*jc+1], aB[1]);
                    aA[2] = fma2(h2.x, phr[2*jc],   aA[2]);
                    aB[2] = fma2(h2.y, phr[2*jc+1], aB[2]);
                    aA[3] = fma2(h3.x, phr[2*jc],   aA[3]);
                    aB[3] = fma2(h3.y, phr[2*jc+1], aB[3]);
                }
                float4 pw;
                float* pwf = (float*)&pw;
#pragma unroll
                for (int r = 0; r < 4; r++) {
                    float x0, x1, x2, x3;
                    unpack2(aA[r], x0, x1);
                    unpack2(aB[r], x2, x3);
                    pwf[r] = (x0 + x1) + (x2 + x3);
                }
                *(float4*)&myslice[tt * 4] = pw;
            }
            // ===== partial |h|^2 (first warp of team) -> slice tail =====
            if (tt < 32) {
                int row = tt >> 3, seg = (tt & 7) * 8;
                const float* hr = &s_h[(tm * 4 + row) * 68 + seg];
                float ss = 0.f;
#pragma unroll
                for (int j = 0; j < 8; j++) ss += hr[j] * hr[j];
#pragma unroll
                for (int o = 4; o; o >>= 1)
                    ss += __shfl_down_sync(0xffffffffu, ss, o, 8);
                if ((tt & 7) == 0)
                    myslice[512 + row] = ss;
            }
            // ===== warp-granular publish: each warp arrives on its own =====
            __syncwarp();
            if ((tt & 31) == 0)
                asm volatile("red.release.gpu.global.add.u32 [%0], 1;"
                             :: "l"(cnt) : "memory");
            // ===== all-thread detect: spin until 16 warp-arrivals =====
            {
                unsigned int v, tg = 16u * (unsigned)t;
                do {
                    asm volatile("ld.acquire.gpu.global.u32 %0, [%1];"
                                 : "=r"(v) : "l"(cnt) : "memory");
                } while (v < tg);
            }

            // ===== fused reduce: 4 slices, partials + hsq, MLP=8 =====
            {
                const float* base = &g_part[((((size_t)buf * NGRP + grp) * 2 + tm)
                                             * GBLK) * SLICE_F];
                float4 u[GBLK], hq[GBLK];
#pragma unroll
                for (int s = 0; s < GBLK; s++) {
                    u[s]  = __ldcg((const float4*)(base + s * SLICE_F + tt * 4));
                    hq[s] = __ldcg((const float4*)(base + s * SLICE_F + 512));
                }
                dsum[0] = (u[0].x + u[1].x) + (u[2].x + u[3].x);
                dsum[1] = (u[0].y + u[1].y) + (u[2].y + u[3].y);
                dsum[2] = (u[0].z + u[1].z) + (u[2].z + u[3].z);
                dsum[3] = (u[0].w + u[1].w) + (u[2].w + u[3].w);
                hh4[0]  = (hq[0].x + hq[1].x) + (hq[2].x + hq[3].x);
                hh4[1]  = (hq[0].y + hq[1].y) + (hq[2].y + hq[3].y);
                hh4[2]  = (hq[0].z + hq[1].z) + (hq[2].z + hq[3].z);
                hh4[3]  = (hq[0].w + hq[1].w) + (hq[2].w + hq[3].w);
            }
        }

        // ===== assemble k, duplicated layout =====
        {
            float kv[4];
#pragma unroll
            for (int r = 0; r < 4; r++) {
                float d2 = (t > 0)
                    ? (a_cur[r] + hh4[r] - 2.f * dsum[r])
                    : a_cur[r];
                kv[r] = __expf(-d2);
            }
            float4* dst = (float4*)&s_kT2[tt * 20 + tm * 8];
            dst[0] = make_float4(kv[0], kv[0], kv[1], kv[1]);
            dst[1] = make_float4(kv[2], kv[2], kv[3], kv[3]);
        }
        // prefetch A(t+1) — latency hidden under the GEMM
        {
            int tn = (t + 1 < T_) ? (t + 1) : (T_ - 1);
#pragma unroll
            for (int r = 0; r < 4; r++)
                a_cur[r] = __ldcg(&g_A[(size_t)tn * B_ * P_ +
                                       (size_t)(grp * 8 + tm * 4 + r) * P_ + tt]);
        }
        bar_named(barid);   // team's kT2 half visible to team

        // ===== phase 2: gate GEMM + state update (team half) =====
        {
            ull afi0 = bfi, ago0 = bgo, afi1 = bfi, ago1 = bgo;
            const float* kbase = &s_kT2[row0 * 2];
            const float* wbase = &s_W[unit * 4];
#pragma unroll 8
            for (int p = 0; p < 128; p++) {
                ulonglong2 w2 = *(const ulonglong2*)(wbase + p * 256);
                ulonglong2 kk = *(const ulonglong2*)(kbase + p * 20);
                afi0 = fma2(kk.x, w2.x, afi0);
                ago0 = fma2(kk.x, w2.y, ago0);
                afi1 = fma2(kk.y, w2.x, afi1);
                ago1 = fma2(kk.y, w2.y, ago1);
            }
            float vf, vi, vg, vo;
            unpack2(afi0, vf, vi); unpack2(ago0, vg, vo);
            {
                float f = sigf(vf), ii = sigf(vi), gg = tanh_fast(vg), o = sigf(vo);
                c0 = f * c0 + ii * gg;
                h0v = o * tanh_fast(c0);
                s_h[row0 * 68 + unit] = h0v;
            }
            unpack2(afi1, vf, vi); unpack2(ago1, vg, vo);
            {
                float f = sigf(vf), ii = sigf(vi), gg = tanh_fast(vg), o = sigf(vo);
                c1 = f * c1 + ii * gg;
                h1v = o * tanh_fast(c1);
                s_h[(row0 + 1) * 68 + unit] = h1v;
            }
            out[(size_t)t * BH_ + idx0] = h0v;
            out[(size_t)t * BH_ + idx1] = h1v;
        }
        bar_named(barid);   // team's h visible before next phase1
    }

    // final hx / cx
    out[OUT_H + idx0] = h0v;
    out[OUT_H + BH_ + idx0] = c0;
    out[OUT_H + idx1] = h1v;
    out[OUT_H + BH_ + idx1] = c1;
}

// ---------------- launch ----------------------------------------------------
extern "C" void kernel_launch(void* const* d_in, const int* in_sizes, int n_in,
                              void* d_out, int out_size) {
    const float* x     = (const float*)d_in[0];
    const float* proto = (const float*)d_in[1];
    const float* Wf    = (const float*)d_in[2];
    const float* bf    = (const float*)d_in[3];
    const float* Wi    = (const float*)d_in[4];
    const float* bi    = (const float*)d_in[5];
    const float* Wg    = (const float*)d_in[6];
    const float* bg    = (const float*)d_in[7];
    const float* Wo    = (const float*)d_in[8];
    const float* bo    = (const float*)d_in[9];
    float* out = (float*)d_out;

    const int smem_bytes = SMEM_FLOATS * (int)sizeof(float);
    cudaFuncSetAttribute(qlstm_main, cudaFuncAttributeMaxDynamicSharedMemorySize,
                         smem_bytes);

    zero_cnt_kernel<<<2, 1024>>>();
    xsq_kernel<<<M_ / 8, 256>>>(x);
    psum_kernel<<<1, 128>>>(proto);
    agemm_kernel<<<M_ / 64, 256>>>(x, proto);
    qlstm_main<<<NBLK, NTHR, smem_bytes>>>(proto, Wf, bf, Wi, bi, Wg, bg, Wo, bo, out);
}